// round 3
// baseline (speedup 1.0000x reference)
#include <cuda_runtime.h>
#include <math.h>

// Problem constants
#define BATCH 512
#define DL    64
#define HID   64
#define DP1   65          // D_L + 1
#define IJ    4225        // 65*65  (GEMM K, true)
#define KPAD  4240        // 265*16 (GEMM K, padded to BK multiple)
#define NG    4160        // 65*64  (GEMM N)

// Scratch (allocation-free rule: __device__ globals)
__device__ float g_R[BATCH * KPAD];   // [512, 4240] row-major, zero-padded cols >= 4225
__device__ float g_Q[BATCH * NG];     // [512, 4160] row-major

// ---------------------------------------------------------------------------
// Kernel 1: R[b, i*65+j] = a_h[b,i] * v_h[b,j]   (a_h/v_h have leading 1)
// ---------------------------------------------------------------------------
__global__ void fill_R(const float* __restrict__ a, const float* __restrict__ v) {
    int idx = blockIdx.x * blockDim.x + threadIdx.x;
    const int total = BATCH * KPAD;
    const int stride = gridDim.x * blockDim.x;
    for (; idx < total; idx += stride) {
        int b = idx / KPAD;
        int c = idx - b * KPAD;
        float val = 0.0f;
        if (c < IJ) {
            int i = c / DP1;
            int j = c - i * DP1;
            float av = (i == 0) ? 1.0f : a[b * DL + (i - 1)];
            float vv = (j == 0) ? 1.0f : v[b * DL + (j - 1)];
            val = av * vv;
        }
        g_R[idx] = val;
    }
}

// ---------------------------------------------------------------------------
// Kernel 2: Q[512,4160] = R[512,4225] @ W1v[4225,4160]
//   W1 [274625,64] row-major reinterpreted in place as [4225, 4160] row-major.
//   Tiling: BM=128, BN=64, BK=16; 256 threads; 8x4 accum per thread.
//   Grid = (4160/64, 512/128) = (65, 4) = 260 blocks -> ~one resident wave.
// ---------------------------------------------------------------------------
__global__ __launch_bounds__(256) void sgemm(const float* __restrict__ Bm) {
    __shared__ float As[16][128];   // k-major A tile
    __shared__ float Bs[16][64];

    const int bn = blockIdx.x;            // 0..64
    const int bm = blockIdx.y;            // 0..3
    const int tid = threadIdx.x;
    const int tm = tid >> 4;              // 0..15 -> 8 rows each
    const int tn = tid & 15;              // 0..15 -> 4 cols each
    const int row0 = bm * 128;
    const int col0 = bn * 64;

    // A-tile load mapping: 512 float4 per tile, 2 per thread
    const int arow = tid >> 2;            // 0..63
    const int ak4  = (tid & 3) * 4;       // 0,4,8,12
    // B-tile load mapping: 256 float4 per tile, 1 per thread
    const int brow = tid >> 4;            // 0..15
    const int bc4  = (tid & 15) * 4;      // 0..60

    float acc[8][4];
    #pragma unroll
    for (int i = 0; i < 8; ++i)
        #pragma unroll
        for (int j = 0; j < 4; ++j) acc[i][j] = 0.0f;

    for (int kt = 0; kt < KPAD / 16; ++kt) {
        const int k0 = kt * 16;

        // Load A tile (g_R), transpose into k-major smem
        #pragma unroll
        for (int p = 0; p < 2; ++p) {
            int r = arow + p * 64;
            const float4 f = *reinterpret_cast<const float4*>(
                &g_R[(size_t)(row0 + r) * KPAD + k0 + ak4]);
            As[ak4 + 0][r] = f.x;
            As[ak4 + 1][r] = f.y;
            As[ak4 + 2][r] = f.z;
            As[ak4 + 3][r] = f.w;
        }
        // Load B tile (W1v), guard the K remainder (4225..4239 -> 0)
        {
            const int kg = k0 + brow;
            float4 f = make_float4(0.f, 0.f, 0.f, 0.f);
            if (kg < IJ)
                f = *reinterpret_cast<const float4*>(
                    &Bm[(size_t)kg * NG + col0 + bc4]);
            *reinterpret_cast<float4*>(&Bs[brow][bc4]) = f;
        }
        __syncthreads();

        #pragma unroll
        for (int kk = 0; kk < 16; ++kk) {
            float ra[8], rb[4];
            const float4 a0 = *reinterpret_cast<const float4*>(&As[kk][tm * 8]);
            const float4 a1 = *reinterpret_cast<const float4*>(&As[kk][tm * 8 + 4]);
            ra[0] = a0.x; ra[1] = a0.y; ra[2] = a0.z; ra[3] = a0.w;
            ra[4] = a1.x; ra[5] = a1.y; ra[6] = a1.z; ra[7] = a1.w;
            const float4 b0 = *reinterpret_cast<const float4*>(&Bs[kk][tn * 4]);
            rb[0] = b0.x; rb[1] = b0.y; rb[2] = b0.z; rb[3] = b0.w;
            #pragma unroll
            for (int i = 0; i < 8; ++i)
                #pragma unroll
                for (int j = 0; j < 4; ++j)
                    acc[i][j] = fmaf(ra[i], rb[j], acc[i][j]);
        }
        __syncthreads();
    }

    // Store C tile
    #pragma unroll
    for (int i = 0; i < 8; ++i) {
        const int row = row0 + tm * 8 + i;
        float4 o;
        o.x = acc[i][0]; o.y = acc[i][1]; o.z = acc[i][2]; o.w = acc[i][3];
        *reinterpret_cast<float4*>(&g_Q[(size_t)row * NG + col0 + tn * 4]) = o;
    }
}

// ---------------------------------------------------------------------------
// Kernel 3: per-batch tail.
//   out1[h] = tanh(b1[h] + sum_k t_h[k] * Q[b, k*64+h])
//   h2 = tanh(out1 @ W2 + b2); out = tanh(h2 @ W3 + b3)
// One block (64 threads) per batch element.
// ---------------------------------------------------------------------------
__global__ __launch_bounds__(64) void tail_kernel(
    const float* __restrict__ l,
    const float* __restrict__ b1,
    const float* __restrict__ W2, const float* __restrict__ b2,
    const float* __restrict__ W3, const float* __restrict__ b3,
    float* __restrict__ out)
{
    __shared__ float t[DP1];
    __shared__ float h1[HID];
    __shared__ float h2[HID];

    const int b = blockIdx.x;
    const int h = threadIdx.x;   // 0..63

    if (h == 0) t[0] = 1.0f;
    t[h + 1] = l[b * DL + h];
    __syncthreads();

    const float* q = &g_Q[(size_t)b * NG];
    float acc = b1[h];
    #pragma unroll
    for (int k = 0; k < DP1; ++k)
        acc = fmaf(t[k], q[k * HID + h], acc);
    h1[h] = tanhf(acc);
    __syncthreads();

    acc = b2[h];
    #pragma unroll
    for (int j = 0; j < HID; ++j)
        acc = fmaf(h1[j], W2[j * HID + h], acc);
    h2[h] = tanhf(acc);
    __syncthreads();

    acc = b3[h];
    #pragma unroll
    for (int j = 0; j < HID; ++j)
        acc = fmaf(h2[j], W3[j * HID + h], acc);
    out[b * DL + h] = tanhf(acc);
}

// ---------------------------------------------------------------------------
// Launch
// ---------------------------------------------------------------------------
extern "C" void kernel_launch(void* const* d_in, const int* in_sizes, int n_in,
                              void* d_out, int out_size)
{
    (void)in_sizes; (void)n_in; (void)out_size;

    const float* l  = (const float*)d_in[0];
    const float* a  = (const float*)d_in[1];
    const float* v  = (const float*)d_in[2];
    const float* W1 = (const float*)d_in[3];
    const float* b1 = (const float*)d_in[4];
    const float* W2 = (const float*)d_in[5];
    const float* b2 = (const float*)d_in[6];
    const float* W3 = (const float*)d_in[7];
    const float* b3 = (const float*)d_in[8];
    float* out = (float*)d_out;

    fill_R<<<512, 256>>>(a, v);

    dim3 grid(NG / 64, BATCH / 128);   // (65, 4)
    sgemm<<<grid, 256>>>(W1);

    tail_kernel<<<BATCH, 64>>>(l, b1, W2, b2, W3, b3, out);
}

// round 6
// speedup vs baseline: 3.0648x; 3.0648x over previous
#include <cuda_runtime.h>
#include <math.h>
#include <stdint.h>

// ---------------------------------------------------------------------------
// Problem constants
// ---------------------------------------------------------------------------
#define BATCH 512
#define DL    64
#define HID   64
#define DP1   65           // D_L + 1
#define IJ    4225         // GEMM K (true) = 65*65
#define KP    4256         // GEMM K padded = 133*32
#define NG    4160         // GEMM N = 65*64
#define NKT   133          // K tiles of 32
#define BM    128
#define BN    64
#define ROWP  36           // smem row pitch in floats (bank-conflict-free frags)

// Scratch (__device__ globals; allocation-free rule). 16B-aligned for cp.async/float4.
__device__ __align__(16) float g_R [BATCH * KP];      // [512][4256], tf32-rounded, K-padded 0
__device__ __align__(16) float g_Wt[(size_t)NG * KP]; // [4160][4256] W1v^T, tf32-rounded
__device__ __align__(16) float g_Q [BATCH * NG];      // [512][4160]

// ---------------------------------------------------------------------------
// Small PTX helpers (all sm_80-era: legal on plain sm_100 target)
// ---------------------------------------------------------------------------
__device__ __forceinline__ float to_tf32(float x) {
    uint32_t u;
    asm("cvt.rna.tf32.f32 %0, %1;" : "=r"(u) : "f"(x));
    return __uint_as_float(u);
}
__device__ __forceinline__ uint32_t smem_u32(const void* p) {
    uint32_t a;
    asm("{ .reg .u64 t; cvta.to.shared.u64 t, %1; cvt.u32.u64 %0, t; }"
        : "=r"(a) : "l"(p));
    return a;
}
#define CP_ASYNC16(dst, src) \
    asm volatile("cp.async.ca.shared.global [%0], [%1], 16;" \
                 :: "r"(dst), "l"(src))
#define CP_COMMIT() asm volatile("cp.async.commit_group;" ::: "memory")
#define CP_WAIT(n)  asm volatile("cp.async.wait_group %0;" :: "n"(n) : "memory")

#define LDSM_X4(r0, r1, r2, r3, addr) \
    asm volatile("ldmatrix.sync.aligned.m8n8.x4.shared.b16 {%0,%1,%2,%3}, [%4];" \
                 : "=r"(r0), "=r"(r1), "=r"(r2), "=r"(r3) : "r"(addr))

#define MMA_TF32(c, a, b) \
    asm volatile("mma.sync.aligned.m16n8k8.row.col.f32.tf32.tf32.f32 " \
                 "{%0,%1,%2,%3}, {%4,%5,%6,%7}, {%8,%9}, {%0,%1,%2,%3};" \
                 : "+f"((c)[0]), "+f"((c)[1]), "+f"((c)[2]), "+f"((c)[3]) \
                 : "r"((a)[0]), "r"((a)[1]), "r"((a)[2]), "r"((a)[3]), \
                   "r"((b)[0]), "r"((b)[1]))

// ---------------------------------------------------------------------------
// Kernel 1: R[b, i*65+j] = tf32(a_h[b,i] * v_h[b,j]); K-padded with zeros
// ---------------------------------------------------------------------------
__global__ __launch_bounds__(256) void fill_R(const float* __restrict__ a,
                                              const float* __restrict__ v) {
    __shared__ float sa[DP1], sv[DP1];
    const int b = blockIdx.x;
    const int t = threadIdx.x;
    if (t == 0) { sa[0] = 1.0f; sv[0] = 1.0f; }
    if (t < DL) { sa[t + 1] = a[b * DL + t]; sv[t + 1] = v[b * DL + t]; }
    __syncthreads();
    for (int c = t; c < KP; c += 256) {
        float val = 0.0f;
        if (c < IJ) {
            int i = c / DP1;
            int j = c - i * DP1;
            val = to_tf32(sa[i] * sv[j]);
        }
        g_R[b * KP + c] = val;
    }
}

// ---------------------------------------------------------------------------
// Kernel 2: g_Wt[n][k] = tf32(W1v[k][n]); W1 [274625,64] viewed as [4225,4160]
// grid (133, 130), block (32, 8)
// ---------------------------------------------------------------------------
__global__ __launch_bounds__(256) void transpose_W(const float* __restrict__ W) {
    __shared__ float tile[32][33];
    const int kb = blockIdx.x * 32;
    const int nb = blockIdx.y * 32;
    const int tx = threadIdx.x, ty = threadIdx.y;
    #pragma unroll
    for (int i = 0; i < 32; i += 8) {
        int k = kb + ty + i;
        float val = 0.0f;
        if (k < IJ) val = to_tf32(W[(size_t)k * NG + nb + tx]);
        tile[ty + i][tx] = val;
    }
    __syncthreads();
    #pragma unroll
    for (int i = 0; i < 32; i += 8) {
        int n = nb + ty + i;
        g_Wt[(size_t)n * KP + kb + tx] = tile[tx][ty + i];
    }
}

// ---------------------------------------------------------------------------
// Kernel 3: tf32 mma.sync GEMM  Q[512,4160] = R @ W1v
//   BM=128 x BN=64, BK=32, 3-stage cp.async pipeline, 256 threads.
//   Warp grid 4x2, warp tile 32x32 (2 m16 tiles x 4 n8 tiles).
//   Smem: A 3x[128][36]f @0 (55296 B), B 3x[64][36]f @55296 (27648 B) = 82944 B.
// ---------------------------------------------------------------------------
#define AS_STAGE (BM * ROWP * 4)          // 18432 B
#define BS_STAGE (BN * ROWP * 4)          // 9216 B
#define BS_BASE  (3 * AS_STAGE)           // 55296
#define SMEM_BYTES (3 * AS_STAGE + 3 * BS_STAGE)  // 82944

__global__ __launch_bounds__(256) void gemm_tf32(void) {
    extern __shared__ char smem[];
    const uint32_t sb = smem_u32(smem);
    const int tid = threadIdx.x;
    const int wid = tid >> 5;
    const int lid = tid & 31;
    const int wr  = wid >> 1;             // 0..3  -> 32-row band
    const int wc  = wid & 1;              // 0..1  -> 32-col band
    const int row0 = blockIdx.y * BM;
    const int col0 = blockIdx.x * BN;

    // cp.async load mapping
    const int ldr = tid >> 3;             // 0..31 (row within 32-row slab)
    const int ldq = tid & 7;              // 16B chunk within 32-float row
    const float* asrc = &g_R [(size_t)row0 * KP + ldq * 4];
    const float* bsrc = &g_Wt[(size_t)col0 * KP + ldq * 4];

    // Fragment smem offsets (floats), hoisted
    const int fm = lid >> 3;              // matrix id 0..3
    const int fr = lid & 7;               // row within matrix
    // A: matrix&1 -> +8 rows; matrix>>1 -> +4 fcols
    int aoff[2], boff[2];
    #pragma unroll
    for (int mt = 0; mt < 2; ++mt)
        aoff[mt] = (wr * 32 + mt * 16 + fr + ((fm & 1) << 3)) * ROWP + ((fm >> 1) << 2);
    // B: matrix>>1 -> +8 n-rows; matrix&1 -> +4 fcols (k)
    #pragma unroll
    for (int np = 0; np < 2; ++np)
        boff[np] = (wc * 32 + np * 16 + ((fm >> 1) << 3) + fr) * ROWP + ((fm & 1) << 2);

    float acc[2][4][4];
    #pragma unroll
    for (int mt = 0; mt < 2; ++mt)
        #pragma unroll
        for (int nt = 0; nt < 4; ++nt)
            #pragma unroll
            for (int e = 0; e < 4; ++e) acc[mt][nt][e] = 0.0f;

    // ---- tile loader (stage s, k-tile kt) ----
    auto load_tile = [&](int kt, int s) {
        const uint32_t ab = sb + s * AS_STAGE;
        const uint32_t bb = sb + BS_BASE + s * BS_STAGE;
        const size_t koff = (size_t)kt * 32;
        #pragma unroll
        for (int p = 0; p < 4; ++p) {          // A: 128 rows
            int r = ldr + p * 32;
            CP_ASYNC16(ab + (r * ROWP + ldq * 4) * 4,
                       asrc + (size_t)r * KP + koff);
        }
        #pragma unroll
        for (int p = 0; p < 2; ++p) {          // B: 64 rows
            int r = ldr + p * 32;
            CP_ASYNC16(bb + (r * ROWP + ldq * 4) * 4,
                       bsrc + (size_t)r * KP + koff);
        }
        CP_COMMIT();
    };

    load_tile(0, 0);
    load_tile(1, 1);

    int stage = 0;
    for (int kt = 0; kt < NKT; ++kt) {
        if (kt < NKT - 1) { CP_WAIT(1); } else { CP_WAIT(0); }
        __syncthreads();
        if (kt + 2 < NKT) load_tile(kt + 2, (stage + 2) % 3);

        const uint32_t ab = sb + stage * AS_STAGE;
        const uint32_t bb = sb + BS_BASE + stage * BS_STAGE;
        #pragma unroll
        for (int ks = 0; ks < 4; ++ks) {
            uint32_t af[2][4], bf[4][2];
            #pragma unroll
            for (int mt = 0; mt < 2; ++mt)
                LDSM_X4(af[mt][0], af[mt][1], af[mt][2], af[mt][3],
                        ab + (aoff[mt] + ks * 8) * 4);
            #pragma unroll
            for (int np = 0; np < 2; ++np)
                LDSM_X4(bf[2 * np][0], bf[2 * np][1], bf[2 * np + 1][0], bf[2 * np + 1][1],
                        bb + (boff[np] + ks * 8) * 4);
            #pragma unroll
            for (int mt = 0; mt < 2; ++mt)
                #pragma unroll
                for (int nt = 0; nt < 4; ++nt)
                    MMA_TF32(acc[mt][nt], af[mt], bf[nt]);
        }
        stage = (stage + 1) % 3;
    }

    // Epilogue: direct global stores (float2 pairs, coalesced within quads)
    const int cr = lid >> 2;              // 0..7
    const int cc = (lid & 3) * 2;         // 0,2,4,6
    #pragma unroll
    for (int mt = 0; mt < 2; ++mt) {
        const int rbase = row0 + wr * 32 + mt * 16 + cr;
        #pragma unroll
        for (int nt = 0; nt < 4; ++nt) {
            const int cbase = col0 + wc * 32 + nt * 8 + cc;
            *reinterpret_cast<float2*>(&g_Q[(size_t)rbase * NG + cbase]) =
                make_float2(acc[mt][nt][0], acc[mt][nt][1]);
            *reinterpret_cast<float2*>(&g_Q[(size_t)(rbase + 8) * NG + cbase]) =
                make_float2(acc[mt][nt][2], acc[mt][nt][3]);
        }
    }
}

// ---------------------------------------------------------------------------
// Kernel 4: per-batch tail (fp32)
// ---------------------------------------------------------------------------
__global__ __launch_bounds__(64) void tail_kernel(
    const float* __restrict__ l,
    const float* __restrict__ b1,
    const float* __restrict__ W2, const float* __restrict__ b2,
    const float* __restrict__ W3, const float* __restrict__ b3,
    float* __restrict__ out)
{
    __shared__ float t[DP1];
    __shared__ float h1[HID];
    __shared__ float h2[HID];

    const int b = blockIdx.x;
    const int h = threadIdx.x;

    if (h == 0) t[0] = 1.0f;
    t[h + 1] = l[b * DL + h];
    __syncthreads();

    const float* q = &g_Q[(size_t)b * NG];
    float acc = b1[h];
    #pragma unroll
    for (int k = 0; k < DP1; ++k)
        acc = fmaf(t[k], q[k * HID + h], acc);
    h1[h] = tanhf(acc);
    __syncthreads();

    acc = b2[h];
    #pragma unroll
    for (int j = 0; j < HID; ++j)
        acc = fmaf(h1[j], W2[j * HID + h], acc);
    h2[h] = tanhf(acc);
    __syncthreads();

    acc = b3[h];
    #pragma unroll
    for (int j = 0; j < HID; ++j)
        acc = fmaf(h2[j], W3[j * HID + h], acc);
    out[b * DL + h] = tanhf(acc);
}

// ---------------------------------------------------------------------------
// Launch
// ---------------------------------------------------------------------------
extern "C" void kernel_launch(void* const* d_in, const int* in_sizes, int n_in,
                              void* d_out, int out_size)
{
    (void)in_sizes; (void)n_in; (void)out_size;

    const float* l  = (const float*)d_in[0];
    const float* a  = (const float*)d_in[1];
    const float* v  = (const float*)d_in[2];
    const float* W1 = (const float*)d_in[3];
    const float* b1 = (const float*)d_in[4];
    const float* W2 = (const float*)d_in[5];
    const float* b2 = (const float*)d_in[6];
    const float* W3 = (const float*)d_in[7];
    const float* b3 = (const float*)d_in[8];
    float* out = (float*)d_out;

    // Unconditional (no static guards). Graph-capture-safe, idempotent.
    cudaFuncSetAttribute(gemm_tf32, cudaFuncAttributeMaxDynamicSharedMemorySize,
                         SMEM_BYTES);

    fill_R<<<BATCH, 256>>>(a, v);

    dim3 tgrid(KP / 32, NG / 32);   // (133, 130)
    dim3 tblk(32, 8);
    transpose_W<<<tgrid, tblk>>>(W1);

    dim3 ggrid(NG / BN, BATCH / BM);  // (65, 4) = 260 CTAs, occ 2 -> one wave
    gemm_tf32<<<ggrid, 256, SMEM_BYTES>>>();

    tail_kernel<<<BATCH, 64>>>(l, b1, W2, b2, W3, b3, out);
}

// round 8
// speedup vs baseline: 3.1246x; 1.0195x over previous
#include <cuda_runtime.h>
#include <math.h>
#include <stdint.h>

// ---------------------------------------------------------------------------
// Problem constants
// ---------------------------------------------------------------------------
#define BATCH 512
#define DL    64
#define HID   64
#define DP1   65           // D_L + 1
#define IJ    4225         // GEMM K (true) = 65*65
#define KP    4256         // GEMM K padded = 133*32
#define NG    4160         // GEMM N = 65*64
#define NKT   133          // K tiles of 32
#define BM    128
#define BN    64
#define ROWPA 36           // A smem row pitch (floats): ldmatrix conflict-free
#define ROWPB 72           // B smem row pitch (floats): 72%32=8 -> 8k+n distinct banks

// Scratch (__device__ globals; allocation-free rule). 16B-aligned.
__device__ __align__(16) float g_R[BATCH * KP];   // [512][4256] tf32-rounded, K-pad 0
__device__ __align__(16) float g_Q[BATCH * NG];   // [512][4160]
__device__ __align__(16) float g_H[BATCH * HID];  // stage-1 tail output

// ---------------------------------------------------------------------------
// PTX helpers (sm_80-era only: legal on plain sm_100 target)
// ---------------------------------------------------------------------------
__device__ __forceinline__ float to_tf32(float x) {
    uint32_t u;
    asm("cvt.rna.tf32.f32 %0, %1;" : "=r"(u) : "f"(x));
    return __uint_as_float(u);
}
__device__ __forceinline__ uint32_t cvt_tf32_u(float x) {
    uint32_t u;
    asm("cvt.rna.tf32.f32 %0, %1;" : "=r"(u) : "f"(x));
    return u;
}
__device__ __forceinline__ uint32_t smem_u32(const void* p) {
    uint32_t a;
    asm("{ .reg .u64 t; cvta.to.shared.u64 t, %1; cvt.u32.u64 %0, t; }"
        : "=r"(a) : "l"(p));
    return a;
}
#define CP_ASYNC16(dst, src) \
    asm volatile("cp.async.ca.shared.global [%0], [%1], 16;" \
                 :: "r"(dst), "l"(src))
// zero-fill variant: copies src_sz bytes (0 or 16), zero-fills the rest
#define CP_ASYNC16_Z(dst, src, src_sz) \
    asm volatile("cp.async.ca.shared.global [%0], [%1], 16, %2;" \
                 :: "r"(dst), "l"(src), "r"(src_sz))
#define CP_COMMIT() asm volatile("cp.async.commit_group;" ::: "memory")
#define CP_WAIT(n)  asm volatile("cp.async.wait_group %0;" :: "n"(n) : "memory")

#define LDSM_X4(r0, r1, r2, r3, addr) \
    asm volatile("ldmatrix.sync.aligned.m8n8.x4.shared.b16 {%0,%1,%2,%3}, [%4];" \
                 : "=r"(r0), "=r"(r1), "=r"(r2), "=r"(r3) : "r"(addr))

#define LDS_F32(out, addr) \
    asm volatile("ld.shared.f32 %0, [%1];" : "=f"(out) : "r"(addr))

#define MMA_TF32(c, a, b) \
    asm volatile("mma.sync.aligned.m16n8k8.row.col.f32.tf32.tf32.f32 " \
                 "{%0,%1,%2,%3}, {%4,%5,%6,%7}, {%8,%9}, {%0,%1,%2,%3};" \
                 : "+f"((c)[0]), "+f"((c)[1]), "+f"((c)[2]), "+f"((c)[3]) \
                 : "r"((a)[0]), "r"((a)[1]), "r"((a)[2]), "r"((a)[3]), \
                   "r"((b)[0]), "r"((b)[1]))

// ---------------------------------------------------------------------------
// Kernel 1: R[b, i*65+j] = tf32(a_h[b,i]*v_h[b,j]); float4 stores; K-pad zeros
// ---------------------------------------------------------------------------
__global__ __launch_bounds__(256) void fill_R(const float* __restrict__ a,
                                              const float* __restrict__ v) {
    __shared__ float sa[DP1], sv[DP1];
    const int b = blockIdx.x;
    const int t = threadIdx.x;
    if (t == 0) { sa[0] = 1.0f; sv[0] = 1.0f; }
    if (t < DL) { sa[t + 1] = a[b * DL + t]; sv[t + 1] = v[b * DL + t]; }
    __syncthreads();
    for (int q = t; q < KP / 4; q += 256) {
        const int c0 = q * 4;
        float4 o;
        float tmp[4];
        #pragma unroll
        for (int e = 0; e < 4; ++e) {
            const int c = c0 + e;
            float val = 0.0f;
            if (c < IJ) {
                int i = c / DP1;
                int j = c - i * DP1;
                val = to_tf32(sa[i] * sv[j]);
            }
            tmp[e] = val;
        }
        o.x = tmp[0]; o.y = tmp[1]; o.z = tmp[2]; o.w = tmp[3];
        *reinterpret_cast<float4*>(&g_R[b * KP + c0]) = o;
    }
}

// ---------------------------------------------------------------------------
// Kernel 2: tf32 mma.sync GEMM  Q[512,4160] = R @ W1v
//   A from g_R (k-contiguous, ldmatrix frags, pitch 36).
//   B DIRECTLY from W1 viewed as Wv[k][n] (n-contiguous): cp.async coalesced,
//   smem [k][n] pitch 72, fragments via scalar LDS + cvt.rna.tf32.
//   BM=128 x BN=64, BK=32, 3-stage pipeline, 256 threads, warp grid 4x2.
//   Smem: A 3x[128][36]f = 55296 B, B 3x[32][72]f = 27648 B -> 82944 B.
// ---------------------------------------------------------------------------
#define AS_STAGE (BM * ROWPA * 4)                 // 18432 B
#define BS_STAGE (32 * ROWPB * 4)                 // 9216 B
#define BS_BASE  (3 * AS_STAGE)                   // 55296
#define SMEM_BYTES (3 * AS_STAGE + 3 * BS_STAGE)  // 82944

__global__ __launch_bounds__(256) void gemm_tf32(const float* __restrict__ W) {
    extern __shared__ char smem[];
    const uint32_t sb = smem_u32(smem);
    const int tid = threadIdx.x;
    const int wid = tid >> 5;
    const int lid = tid & 31;
    const int wr  = wid >> 1;             // 0..3  -> 32-row band
    const int wc  = wid & 1;              // 0..1  -> 32-col band
    const int row0 = blockIdx.y * BM;
    const int col0 = blockIdx.x * BN;

    // A cp.async mapping: 1024 16B chunks/tile; 4 per thread
    const int ldr = tid >> 3;             // 0..31
    const int ldq = tid & 7;              // chunk within 32-float k-row
    const float* asrc = &g_R[(size_t)row0 * KP + ldq * 4];
    // B cp.async mapping: 512 chunks (32 k-rows x 16 n-chunks); 2 per thread
    const int bk_ld = tid >> 3;           // k row 0..31
    const int bnc   = tid & 7;            // n-chunk (plus +8 second pass)
    const float* bsrc = W + (size_t)col0;

    // A fragment offsets (floats): ldmatrix 4-matrix trick
    const int fm = lid >> 3;
    const int fr = lid & 7;
    int aoff[2];
    #pragma unroll
    for (int mt = 0; mt < 2; ++mt)
        aoff[mt] = (wr * 32 + mt * 16 + fr + ((fm & 1) << 3)) * ROWPA + ((fm >> 1) << 2);
    // B fragment base: b0 = B[k=lid%4][n=wc*32 + nt*8 + lid/4]
    const int boff0 = (lid & 3) * ROWPB + wc * 32 + (lid >> 2);

    float acc[2][4][4];
    #pragma unroll
    for (int mt = 0; mt < 2; ++mt)
        #pragma unroll
        for (int nt = 0; nt < 4; ++nt)
            #pragma unroll
            for (int e = 0; e < 4; ++e) acc[mt][nt][e] = 0.0f;

    auto load_tile = [&](int kt, int s) {
        const uint32_t ab = sb + s * AS_STAGE;
        const uint32_t bb = sb + BS_BASE + s * BS_STAGE;
        const size_t koff = (size_t)kt * 32;
        #pragma unroll
        for (int p = 0; p < 4; ++p) {          // A: 128 rows
            int r = ldr + p * 32;
            CP_ASYNC16(ab + (r * ROWPA + ldq * 4) * 4,
                       asrc + (size_t)r * KP + koff);
        }
        {                                       // B: 32 k-rows x 64 n
            const int gk = (int)koff + bk_ld;
            const uint32_t sz = (gk < IJ) ? 16u : 0u;
            const size_t gks = (size_t)(sz ? gk : 0) * NG;
            #pragma unroll
            for (int p = 0; p < 2; ++p) {
                int nc = bnc + p * 8;
                CP_ASYNC16_Z(bb + (bk_ld * ROWPB + nc * 4) * 4,
                             bsrc + gks + nc * 4, sz);
            }
        }
        CP_COMMIT();
    };

    load_tile(0, 0);
    load_tile(1, 1);

    int stage = 0;
    for (int kt = 0; kt < NKT; ++kt) {
        if (kt < NKT - 1) { CP_WAIT(1); } else { CP_WAIT(0); }
        __syncthreads();
        if (kt + 2 < NKT) load_tile(kt + 2, (stage + 2) % 3);

        const uint32_t ab = sb + stage * AS_STAGE;
        const uint32_t bb = sb + BS_BASE + stage * BS_STAGE;
        #pragma unroll
        for (int ks = 0; ks < 4; ++ks) {
            uint32_t af[2][4];
            #pragma unroll
            for (int mt = 0; mt < 2; ++mt)
                LDSM_X4(af[mt][0], af[mt][1], af[mt][2], af[mt][3],
                        ab + (aoff[mt] + ks * 8) * 4);
            uint32_t bf[4][2];
            const uint32_t bks = bb + (boff0 + ks * 8 * ROWPB) * 4;
            #pragma unroll
            for (int nt = 0; nt < 4; ++nt) {
                float x0, x1;
                LDS_F32(x0, bks + nt * 8 * 4);
                LDS_F32(x1, bks + (nt * 8 + 4 * ROWPB) * 4);
                bf[nt][0] = cvt_tf32_u(x0);
                bf[nt][1] = cvt_tf32_u(x1);
            }
            #pragma unroll
            for (int mt = 0; mt < 2; ++mt)
                #pragma unroll
                for (int nt = 0; nt < 4; ++nt)
                    MMA_TF32(acc[mt][nt], af[mt], bf[nt]);
        }
        stage = (stage + 1) % 3;
    }

    // Epilogue: direct global float2 stores
    const int cr = lid >> 2;
    const int cc = (lid & 3) * 2;
    #pragma unroll
    for (int mt = 0; mt < 2; ++mt) {
        const int rbase = row0 + wr * 32 + mt * 16 + cr;
        #pragma unroll
        for (int nt = 0; nt < 4; ++nt) {
            const int cbase = col0 + wc * 32 + nt * 8 + cc;
            *reinterpret_cast<float2*>(&g_Q[(size_t)rbase * NG + cbase]) =
                make_float2(acc[mt][nt][0], acc[mt][nt][1]);
            *reinterpret_cast<float2*>(&g_Q[(size_t)(rbase + 8) * NG + cbase]) =
                make_float2(acc[mt][nt][2], acc[mt][nt][3]);
        }
    }
}

// ---------------------------------------------------------------------------
// Kernel 3: tail stage 1 — h1[b,h] = tanh(b1[h] + sum_k t_h[k]*Q[b,k*64+h])
// 256 threads: 4-way k split (kq) x 64 h; smem reduce.
// ---------------------------------------------------------------------------
__global__ __launch_bounds__(256) void tail1(const float* __restrict__ l,
                                             const float* __restrict__ b1) {
    __shared__ float t[DP1];
    __shared__ float red[4][64];
    const int b  = blockIdx.x;
    const int h  = threadIdx.x & 63;
    const int kq = threadIdx.x >> 6;

    if (threadIdx.x < DP1)
        t[threadIdx.x] = (threadIdx.x == 0) ? 1.0f : l[b * DL + threadIdx.x - 1];
    __syncthreads();

    const float* q = &g_Q[(size_t)b * NG];
    float acc = 0.0f;
    #pragma unroll
    for (int k = kq; k < DP1; k += 4)
        acc = fmaf(t[k], q[k * HID + h], acc);
    red[kq][h] = acc;
    __syncthreads();
    if (kq == 0) {
        float s = red[0][h] + red[1][h] + red[2][h] + red[3][h] + b1[h];
        g_H[b * HID + h] = tanhf(s);
    }
}

// ---------------------------------------------------------------------------
// Kernel 4: tail stage 2 — layers 2 & 3; 4 batches per 256-thread block
// ---------------------------------------------------------------------------
__global__ __launch_bounds__(256) void tail2(
    const float* __restrict__ W2, const float* __restrict__ b2,
    const float* __restrict__ W3, const float* __restrict__ b3,
    float* __restrict__ out)
{
    __shared__ float h1s[4][64];
    __shared__ float h2s[4][64];
    const int sub = threadIdx.x >> 6;     // 0..3
    const int h   = threadIdx.x & 63;
    const int b   = blockIdx.x * 4 + sub;

    h1s[sub][h] = g_H[b * HID + h];
    __syncthreads();

    float acc = b2[h];
    #pragma unroll
    for (int j = 0; j < HID; ++j)
        acc = fmaf(h1s[sub][j], W2[j * HID + h], acc);
    h2s[sub][h] = tanhf(acc);
    __syncthreads();

    acc = b3[h];
    #pragma unroll
    for (int j = 0; j < HID; ++j)
        acc = fmaf(h2s[sub][j], W3[j * HID + h], acc);
    out[b * DL + h] = tanhf(acc);
}

// ---------------------------------------------------------------------------
// Launch
// ---------------------------------------------------------------------------
extern "C" void kernel_launch(void* const* d_in, const int* in_sizes, int n_in,
                              void* d_out, int out_size)
{
    (void)in_sizes; (void)n_in; (void)out_size;

    const float* l  = (const float*)d_in[0];
    const float* a  = (const float*)d_in[1];
    const float* v  = (const float*)d_in[2];
    const float* W1 = (const float*)d_in[3];
    const float* b1 = (const float*)d_in[4];
    const float* W2 = (const float*)d_in[5];
    const float* b2 = (const float*)d_in[6];
    const float* W3 = (const float*)d_in[7];
    const float* b3 = (const float*)d_in[8];
    float* out = (float*)d_out;

    // Unconditional (no static guards). Graph-capture-safe, idempotent.
    cudaFuncSetAttribute(gemm_tf32, cudaFuncAttributeMaxDynamicSharedMemorySize,
                         SMEM_BYTES);

    fill_R<<<BATCH, 256>>>(a, v);

    dim3 ggrid(NG / BN, BATCH / BM);  // (65, 4) = 260 CTAs, 2/SM -> one wave
    gemm_tf32<<<ggrid, 256, SMEM_BYTES>>>(W1);

    tail1<<<BATCH, 256>>>(l, b1);
    tail2<<<BATCH / 4, 256>>>(W2, b2, W3, b3, out);
}